// round 11
// baseline (speedup 1.0000x reference)
#include <cuda_runtime.h>
#include <cuda_fp16.h>
#include <cstdint>

// MultiTaskMLP: f16-hi HMMA (W-hi scaled 2^11) + ONE e4m3 m16n8k32 cross MMA
// per k16, sharing a single f32 accumulator (scale 2^11):
//   a*b ~= a_hi*b_hi + (a_lo*b_hi + a_hi*b_lo)     [lo*lo ~2^-24 dropped]
// cross K-concat: A'=[a_lo*2^9 | a_hi/4], B'=[b_hi*4 | b_lo*2^13]
//   half1: (a_lo*2^9)(b_hi*4)  = 2^11 a_lo b_hi
//   half2: (a_hi/4)(b_lo*2^13) = 2^11 a_hi b_lo
// One CTA = (task t, 128 rows of B); 8 warps of 64x64 tiles; H1 stays in smem.

namespace {

constexpr int Bdim = 4096, Tdim = 128, INdim = 768, Hdim = 256;
constexpr int MT = 128, NTHR = 256;
constexpr int NS1 = INdim / 32;   // 24 k32 stages
constexpr int NS2 = Hdim / 32;    // 8

constexpr float SCL = 2048.0f, INV = 1.0f / 2048.0f;
constexpr float ALO = 512.0f;     // a_lo * 2^9
constexpr float AHI = 0.25f;      // a_hi / 4
constexpr float BHI = 4.0f;       // b_hi * 4
constexpr float BLO = 8192.0f;    // b_lo * 2^13

// smem layout (bytes), stage-1 buffer:
constexpr int XHI_O = 0;          // 128 rows x 80  (64B f16 k32 + pad)
constexpr int XC_O  = 10240;      // 128 rows x 80  (2 fp8 32B blocks + pad)
constexpr int WHI_O = 20480;      // 32 k-rows x 528 (512B f16 n256 + pad)
constexpr int WC_O  = 37376;      // 256 n-rows x 80
constexpr int STG1  = 57856;
// H1 region (aliases stage-1 after layer 1):
constexpr int H1HI_O = 0;         // 128 x 528 f16
constexpr int H1C_O  = 67584;     // 128 x 528 fp8 blocks (16 kb x 32B + pad)
constexpr int R1     = 135168;
constexpr int STG2   = 37376;     // WHI(16896) + WC(20480)
constexpr int SMEM_TOTAL = R1 + 2 * STG2;  // 209920

// -------------------- preprocessed global scratch --------------------
__device__ __align__(16) __half  g_xhi [(size_t)Bdim * INdim];
__device__ __align__(16) uint8_t g_xc  [(size_t)Bdim * (INdim / 16) * 32];
__device__ __align__(16) __half  g_w1hi[(size_t)Tdim * INdim * Hdim];
__device__ __align__(16) uint8_t g_w1c [(size_t)Tdim * Hdim * (INdim / 16) * 32];
__device__ __align__(16) __half  g_w2hi[(size_t)Tdim * Hdim * Hdim];
__device__ __align__(16) uint8_t g_w2c [(size_t)Tdim * Hdim * (Hdim / 16) * 32];

// ------------------------------ helpers ------------------------------
__device__ __forceinline__ uint16_t e4m3x2(float hi, float lo) {
    uint16_t r;  // byte0 = cvt(lo), byte1 = cvt(hi)
    asm("cvt.rn.satfinite.e4m3x2.f32 %0, %1, %2;" : "=h"(r) : "f"(hi), "f"(lo));
    return r;
}
__device__ __forceinline__ uint32_t s2u(const void* p) {
    return (uint32_t)__cvta_generic_to_shared(p);
}
__device__ __forceinline__ void cp16(uint32_t dst, const void* src) {
    asm volatile("cp.async.cg.shared.global [%0], [%1], 16;" :: "r"(dst), "l"(src));
}
__device__ __forceinline__ void cp_commit() {
    asm volatile("cp.async.commit_group;" ::: "memory");
}
template <int N>
__device__ __forceinline__ void cp_wait() {
    asm volatile("cp.async.wait_group %0;" :: "n"(N) : "memory");
}
__device__ __forceinline__ void ldm4(uint32_t (&r)[4], uint32_t a) {
    asm volatile("ldmatrix.sync.aligned.m8n8.x4.shared.b16 {%0,%1,%2,%3}, [%4];"
                 : "=r"(r[0]), "=r"(r[1]), "=r"(r[2]), "=r"(r[3]) : "r"(a));
}
__device__ __forceinline__ void ldm4t(uint32_t (&r)[4], uint32_t a) {
    asm volatile("ldmatrix.sync.aligned.m8n8.x4.trans.shared.b16 {%0,%1,%2,%3}, [%4];"
                 : "=r"(r[0]), "=r"(r[1]), "=r"(r[2]), "=r"(r[3]) : "r"(a));
}
__device__ __forceinline__ void mma_f16(float (&d)[4], const uint32_t (&a)[4],
                                        uint32_t b0, uint32_t b1) {
    asm volatile(
        "mma.sync.aligned.m16n8k16.row.col.f32.f16.f16.f32 "
        "{%0,%1,%2,%3}, {%4,%5,%6,%7}, {%8,%9}, {%0,%1,%2,%3};"
        : "+f"(d[0]), "+f"(d[1]), "+f"(d[2]), "+f"(d[3])
        : "r"(a[0]), "r"(a[1]), "r"(a[2]), "r"(a[3]), "r"(b0), "r"(b1));
}
__device__ __forceinline__ void mma_fp8(float (&d)[4], const uint32_t (&a)[4],
                                        uint32_t b0, uint32_t b1) {
    asm volatile(
        "mma.sync.aligned.m16n8k32.row.col.f32.e4m3.e4m3.f32 "
        "{%0,%1,%2,%3}, {%4,%5,%6,%7}, {%8,%9}, {%0,%1,%2,%3};"
        : "+f"(d[0]), "+f"(d[1]), "+f"(d[2]), "+f"(d[3])
        : "r"(a[0]), "r"(a[1]), "r"(a[2]), "r"(a[3]), "r"(b0), "r"(b1));
}

// ------------------------------ split kernels ------------------------------
// X: per (row, kb16): f16 hi (layout preserved) + 32B fp8 A'-block [lo | hi].
__global__ void split_x(const float* __restrict__ x) {
    int g = blockIdx.x * 256 + threadIdx.x;
    if (g >= Bdim * (INdim / 16)) return;
    int row = g / (INdim / 16), kb = g % (INdim / 16);
    const float* src = x + (size_t)row * INdim + kb * 16;
    float hf[16], lo[16];
    uint32_t hw[8];
#pragma unroll
    for (int q = 0; q < 8; q++) {
        float v0 = src[2 * q], v1 = src[2 * q + 1];
        __half h0 = __float2half_rn(v0), h1 = __float2half_rn(v1);
        hf[2 * q] = __half2float(h0); hf[2 * q + 1] = __half2float(h1);
        lo[2 * q] = v0 - hf[2 * q];   lo[2 * q + 1] = v1 - hf[2 * q + 1];
        __half2 p; p.x = h0; p.y = h1;
        hw[q] = *(uint32_t*)&p;
    }
    uint4* dhi = (uint4*)(g_xhi + (size_t)row * INdim + kb * 16);
    dhi[0] = make_uint4(hw[0], hw[1], hw[2], hw[3]);
    dhi[1] = make_uint4(hw[4], hw[5], hw[6], hw[7]);
    uint32_t loW[4], hiW[4];
#pragma unroll
    for (int q = 0; q < 4; q++) {
        loW[q] = (uint32_t)e4m3x2(lo[4 * q + 1] * ALO, lo[4 * q] * ALO) |
                 ((uint32_t)e4m3x2(lo[4 * q + 3] * ALO, lo[4 * q + 2] * ALO) << 16);
        hiW[q] = (uint32_t)e4m3x2(hf[4 * q + 1] * AHI, hf[4 * q] * AHI) |
                 ((uint32_t)e4m3x2(hf[4 * q + 3] * AHI, hf[4 * q + 2] * AHI) << 16);
    }
    uint4* dc = (uint4*)(g_xc + ((size_t)row * (INdim / 16) + kb) * 32);
    dc[0] = make_uint4(loW[0], loW[1], loW[2], loW[3]);
    dc[1] = make_uint4(hiW[0], hiW[1], hiW[2], hiW[3]);
}

// W-hi: elementwise f16(v * 2^11) (exact pow2 scale), layout preserved [t][k][n].
__global__ void scale_w(const float4* __restrict__ src, int which, int n4) {
    int i = blockIdx.x * 256 + threadIdx.x;
    if (i >= n4) return;
    __half* dst = which ? g_w1hi : g_w2hi;
    float4 v = src[i];
    __half2 p0, p1;
    p0.x = __float2half_rn(v.x * SCL); p0.y = __float2half_rn(v.y * SCL);
    p1.x = __float2half_rn(v.z * SCL); p1.y = __float2half_rn(v.w * SCL);
    ((uint2*)dst)[i] = make_uint2(*(uint32_t*)&p0, *(uint32_t*)&p1);
}

// W cross: transpose [t][k][n] -> [t][n][kb16][ b_hi*4 (16B) | b_lo*2^13 (16B) ].
template <int K, int WHICH>
__global__ void split_wc(const float* __restrict__ src) {
    uint8_t* dst = WHICH ? g_w1c : g_w2c;
    __shared__ float tile[32][33];
    int t = blockIdx.z, k0 = blockIdx.x * 32, n0 = blockIdx.y * 32;
    const float* s = src + (size_t)t * K * Hdim;
    int tx = threadIdx.x, ty = threadIdx.y;
#pragma unroll
    for (int i = 0; i < 32; i += 8)
        tile[ty + i][tx] = s[(size_t)(k0 + ty + i) * Hdim + n0 + tx];
    __syncthreads();
    int kb_l = ty & 1, j4 = ty >> 1;   // this thread: 4 k elems of one block
    float hf[4], lo[4];
#pragma unroll
    for (int jj = 0; jj < 4; jj++) {
        float v = tile[kb_l * 16 + j4 * 4 + jj][tx];
        __half h = __float2half_rn(v);
        hf[jj] = __half2float(h);
        lo[jj] = v - hf[jj];
    }
    uint32_t hiW = (uint32_t)e4m3x2(hf[1] * BHI, hf[0] * BHI) |
                   ((uint32_t)e4m3x2(hf[3] * BHI, hf[2] * BHI) << 16);
    uint32_t loW = (uint32_t)e4m3x2(lo[1] * BLO, lo[0] * BLO) |
                   ((uint32_t)e4m3x2(lo[3] * BLO, lo[2] * BLO) << 16);
    size_t base = (((size_t)t * Hdim + n0 + tx) * (K / 16) + (k0 / 16 + kb_l)) * 32
                  + j4 * 4;
    *(uint32_t*)(dst + base)      = hiW;   // k0-15 half: b_hi*4
    *(uint32_t*)(dst + base + 16) = loW;   // k16-31 half: b_lo*2^13
}

// ------------------------------ main kernel ------------------------------
__global__ void __launch_bounds__(NTHR, 1)
mlp_kernel(const float* __restrict__ b1, const float* __restrict__ b2,
           const float* __restrict__ W3, const float* __restrict__ b3,
           float* __restrict__ out) {
    extern __shared__ char smem[];
    const uint32_t sb = s2u(smem);
    const int tid = threadIdx.x;
    const int lane = tid & 31, w = tid >> 5;
    const int wr = w >> 2, wc = w & 3;                   // 2x4 warps, 64x64 tiles
    const int t = blockIdx.y;
    const int gb0 = blockIdx.x * MT;

    const int lr  = (lane & 7) + 8 * ((lane >> 3) & 1);  // row-in-16 (A / Bt)
    const int lc8 = 8 * (lane >> 4);                     // 16B half select
    const int ncr = (lane & 7) + 8 * (lane >> 4);        // fp8 B: column row
    const int nbo = 16 * ((lane >> 3) & 1);              // fp8 B: k-half byte

    const __half*  xhi = g_xhi + (size_t)gb0 * INdim;
    const uint8_t* xc  = g_xc  + (size_t)gb0 * (INdim / 16) * 32;
    const __half*  w1h = g_w1hi + (size_t)t * INdim * Hdim;
    const uint8_t* w1c = g_w1c  + (size_t)t * Hdim * (INdim / 16) * 32;
    const __half*  w2h = g_w2hi + (size_t)t * Hdim * Hdim;
    const uint8_t* w2c = g_w2c  + (size_t)t * Hdim * (Hdim / 16) * 32;

    float acc[4][8][4];
#pragma unroll
    for (int mi = 0; mi < 4; mi++)
#pragma unroll
        for (int ni = 0; ni < 8; ni++)
#pragma unroll
            for (int r = 0; r < 4; r++) acc[mi][ni][r] = 0.f;

    auto ld1 = [&](int s, int b) {
        const uint32_t S = sb + (b ? STG1 : 0);
        const int k0 = s * 32, kb0 = s * 2;
#pragma unroll
        for (int it = 0; it < 2; it++) {             // XHI + XC (128 x 64B each)
            int idx = it * NTHR + tid;
            int row = idx >> 2, c = (idx & 3) * 16;
            cp16(S + XHI_O + (uint32_t)(row * 80 + c),
                 (const char*)(xhi + (size_t)row * INdim + k0) + c);
            cp16(S + XC_O + (uint32_t)(row * 80 + c),
                 xc + ((size_t)row * (INdim / 16) + kb0) * 32 + c);
        }
#pragma unroll
        for (int it = 0; it < 4; it++) {             // WHI (32x512B) + WC (256x64B)
            int idx = it * NTHR + tid;
            int row = idx >> 5, c = (idx & 31) * 16;
            cp16(S + WHI_O + (uint32_t)(row * 528 + c),
                 (const char*)(w1h + (size_t)(k0 + row) * Hdim) + c);
            int rw = idx >> 2, cw = (idx & 3) * 16;
            cp16(S + WC_O + (uint32_t)(rw * 80 + cw),
                 w1c + ((size_t)rw * (INdim / 16) + kb0) * 32 + cw);
        }
        cp_commit();
    };
    auto ld2 = [&](int s, int b) {
        const uint32_t S = sb + (uint32_t)(R1 + (b ? STG2 : 0));
        const int k0 = s * 32, kb0 = s * 2;
#pragma unroll
        for (int it = 0; it < 4; it++) {
            int idx = it * NTHR + tid;
            int row = idx >> 5, c = (idx & 31) * 16;
            cp16(S + (uint32_t)(row * 528 + c),
                 (const char*)(w2h + (size_t)(k0 + row) * Hdim) + c);
            int rw = idx >> 2, cw = (idx & 3) * 16;
            cp16(S + 16896u + (uint32_t)(rw * 80 + cw),
                 w2c + ((size_t)rw * (Hdim / 16) + kb0) * 32 + cw);
        }
        cp_commit();
    };

    // one k16 slab = 32 f16 hh MMAs then 32 fp8 cross MMAs (shared scaled acc)
    auto slab = [&](uint32_t aHi, int aStride, uint32_t aCr, int aCrStride,
                    uint32_t wHi, uint32_t wCr) {
        uint32_t ah[4][4];
#pragma unroll
        for (int mi = 0; mi < 4; mi++)
            ldm4(ah[mi], aHi + (uint32_t)((wr * 64 + mi * 16 + lr) * aStride
                                          + 2 * lc8));
#pragma unroll
        for (int ni2 = 0; ni2 < 4; ni2++) {
            uint32_t bh[4];
            ldm4t(bh, wHi + (uint32_t)(lr * 528 + (wc * 64 + ni2 * 16 + lc8) * 2));
#pragma unroll
            for (int mi = 0; mi < 4; mi++) {
                mma_f16(acc[mi][2 * ni2],     ah[mi], bh[0], bh[1]);
                mma_f16(acc[mi][2 * ni2 + 1], ah[mi], bh[2], bh[3]);
            }
        }
        uint32_t ac[4][4];
#pragma unroll
        for (int mi = 0; mi < 4; mi++)
            ldm4(ac[mi], aCr + (uint32_t)((wr * 64 + mi * 16 + lr) * aCrStride
                                          + 2 * lc8));
#pragma unroll
        for (int ni2 = 0; ni2 < 4; ni2++) {
            uint32_t bc[4];
            ldm4(bc, wCr + (uint32_t)((wc * 64 + ni2 * 16 + ncr) * 80 + nbo));
#pragma unroll
            for (int mi = 0; mi < 4; mi++) {
                mma_fp8(acc[mi][2 * ni2],     ac[mi], bc[0], bc[1]);
                mma_fp8(acc[mi][2 * ni2 + 1], ac[mi], bc[2], bc[3]);
            }
        }
    };

    // ========================= Layer 1 =========================
    ld1(0, 0);
    for (int s = 0; s < NS1; s++) {
        const int b = s & 1;
        if (s + 1 < NS1) { ld1(s + 1, b ^ 1); cp_wait<1>(); }
        else             { cp_wait<0>(); }
        __syncthreads();
        const uint32_t S = sb + (b ? STG1 : 0);
#pragma unroll
        for (int kk = 0; kk < 2; kk++)
            slab(S + XHI_O + kk * 32, 80, S + XC_O + kk * 32, 80,
                 S + WHI_O + (uint32_t)(kk * 16 * 528), S + WC_O + kk * 32);
        __syncthreads();
    }

    ld2(0, 0);   // prefetch W2 stage 0 under epilogue 1

    // == Epilogue 1: descale, bias, relu; write H1 f16-hi + fp8 A' to smem ==
    {
        const float* b1t = b1 + t * Hdim;
#pragma unroll
        for (int mi = 0; mi < 4; mi++)
#pragma unroll
            for (int ni = 0; ni < 8; ni++) {
                const int c = wc * 64 + ni * 8 + (lane & 3) * 2;
                const float2 bb = *(const float2*)(b1t + c);
#pragma unroll
                for (int h = 0; h < 2; h++) {
                    const int row = wr * 64 + mi * 16 + (lane >> 2) + 8 * h;
                    float v0 = fmaxf(fmaf(acc[mi][ni][2 * h],     INV, bb.x), 0.f);
                    float v1 = fmaxf(fmaf(acc[mi][ni][2 * h + 1], INV, bb.y), 0.f);
                    __half h0 = __float2half_rn(v0), h1 = __float2half_rn(v1);
                    float f0 = __half2float(h0), f1 = __half2float(h1);
                    __half2 hp; hp.x = h0; hp.y = h1;
                    *(uint32_t*)(smem + H1HI_O + row * 528 + c * 2) = *(uint32_t*)&hp;
                    uint32_t co = H1C_O + row * 528 + (c >> 4) * 32 + (c & 15);
                    *(uint16_t*)(smem + co) =
                        e4m3x2((v1 - f1) * ALO, (v0 - f0) * ALO);
                    *(uint16_t*)(smem + co + 16) = e4m3x2(f1 * AHI, f0 * AHI);
                    acc[mi][ni][2 * h] = 0.f;
                    acc[mi][ni][2 * h + 1] = 0.f;
                }
            }
    }

    // ========================= Layer 2 =========================
    for (int s = 0; s < NS2; s++) {
        const int b = s & 1;
        if (s + 1 < NS2) { ld2(s + 1, b ^ 1); cp_wait<1>(); }
        else             { cp_wait<0>(); }
        __syncthreads();   // also orders epilogue-1 H1 writes before reads
        const uint32_t S = sb + (uint32_t)(R1 + (b ? STG2 : 0));
#pragma unroll
        for (int kk = 0; kk < 2; kk++)
            slab(sb + H1HI_O + (uint32_t)((s * 32 + kk * 16) * 2), 528,
                 sb + H1C_O + (uint32_t)((s * 2 + kk) * 32), 528,
                 S + (uint32_t)(kk * 16 * 528), S + 16896u + kk * 32);
        __syncthreads();
    }

    // ======= Epilogue 2 + Layer 3: out = relu(H2).W3 + b3 =======
    {
        const float* b2t = b2 + t * Hdim;
        const float* w3t = W3 + t * Hdim;
        float p[4][2];
#pragma unroll
        for (int mi = 0; mi < 4; mi++) { p[mi][0] = 0.f; p[mi][1] = 0.f; }
#pragma unroll
        for (int ni = 0; ni < 8; ni++) {
            const int c = wc * 64 + ni * 8 + (lane & 3) * 2;
            const float2 bb = *(const float2*)(b2t + c);
            const float2 ww = *(const float2*)(w3t + c);
#pragma unroll
            for (int mi = 0; mi < 4; mi++)
#pragma unroll
                for (int h = 0; h < 2; h++) {
                    float v0 = fmaxf(fmaf(acc[mi][ni][2 * h],     INV, bb.x), 0.f);
                    float v1 = fmaxf(fmaf(acc[mi][ni][2 * h + 1], INV, bb.y), 0.f);
                    p[mi][h] += v0 * ww.x + v1 * ww.y;
                }
        }
        float* red = (float*)(smem + R1);   // [128][4] staging (stage bufs dead)
        __syncthreads();
#pragma unroll
        for (int mi = 0; mi < 4; mi++)
#pragma unroll
            for (int h = 0; h < 2; h++) {
                float v = p[mi][h];
                v += __shfl_xor_sync(0xffffffffu, v, 1);
                v += __shfl_xor_sync(0xffffffffu, v, 2);
                if ((lane & 3) == 0) {
                    const int row = wr * 64 + mi * 16 + (lane >> 2) + 8 * h;
                    red[row * 4 + wc] = v;
                }
            }
        __syncthreads();
        if (tid < MT) {
            float s4 = red[tid * 4] + red[tid * 4 + 1] +
                       red[tid * 4 + 2] + red[tid * 4 + 3] + __ldg(b3 + t);
            out[(size_t)(gb0 + tid) * Tdim + t] = s4;
        }
    }
}

}  // namespace

extern "C" void kernel_launch(void* const* d_in, const int* in_sizes, int n_in,
                              void* d_out, int out_size) {
    const float* x  = (const float*)d_in[0];
    const float* W1 = (const float*)d_in[1];
    const float* b1 = (const float*)d_in[2];
    const float* W2 = (const float*)d_in[3];
    const float* b2 = (const float*)d_in[4];
    const float* W3 = (const float*)d_in[5];
    const float* b3 = (const float*)d_in[6];
    float* out = (float*)d_out;

    split_x<<<(Bdim * (INdim / 16) + 255) / 256, 256>>>(x);
    const int n41 = Tdim * INdim * Hdim / 4;
    const int n42 = Tdim * Hdim * Hdim / 4;
    scale_w<<<(n41 + 255) / 256, 256>>>((const float4*)W1, 1, n41);
    scale_w<<<(n42 + 255) / 256, 256>>>((const float4*)W2, 0, n42);
    split_wc<INdim, 1><<<dim3(INdim / 32, Hdim / 32, Tdim), dim3(32, 8)>>>(W1);
    split_wc<Hdim,  0><<<dim3(Hdim  / 32, Hdim / 32, Tdim), dim3(32, 8)>>>(W2);

    cudaFuncSetAttribute(mlp_kernel,
                         cudaFuncAttributeMaxDynamicSharedMemorySize, SMEM_TOTAL);
    dim3 grid(Bdim / MT, Tdim);  // b-block fastest: wave shares few tasks' W in L2
    mlp_kernel<<<grid, NTHR, SMEM_TOTAL>>>(b1, b2, W3, b3, out);
}

// round 12
// speedup vs baseline: 1.0190x; 1.0190x over previous
#include <cuda_runtime.h>
#include <cuda_fp16.h>
#include <cstdint>

// MultiTaskMLP: f16-hi HMMA (W-hi scaled 2^11) + ONE e4m3 m16n8k32 cross MMA
// per k16, sharing a single f32 accumulator (scale 2^11):
//   a*b ~= a_hi*b_hi + (a_lo*b_hi + a_hi*b_lo)     [lo*lo ~2^-24 dropped]
// cross K-concat: A'=[a_lo*2^9 | a_hi/4], B'=[b_hi*4 | b_lo*2^13].
// R12: fused/coalesced prep ([t][kb][n] cross layout, 32B-block stores),
//      contiguous cp.async spans, one __syncthreads per pipeline stage.

namespace {

constexpr int Bdim = 4096, Tdim = 128, INdim = 768, Hdim = 256;
constexpr int MT = 128, NTHR = 256;
constexpr int NS1 = INdim / 32;   // 24 k32 stages
constexpr int NS2 = Hdim / 32;    // 8

constexpr float SCL = 2048.0f, INV = 1.0f / 2048.0f;
constexpr float ALO = 512.0f;     // a_lo * 2^9
constexpr float AHI = 0.25f;      // a_hi / 4
constexpr float BHI = 4.0f;       // b_hi * 4
constexpr float BLO = 8192.0f;    // b_lo * 2^13

// smem layout (bytes), stage-1 buffer:
constexpr int XHI_O = 0;          // 128 rows x 80  (64B f16 k32 + pad)
constexpr int XC_O  = 10240;      // 128 rows x 80  (2 fp8 32B blocks + pad)
constexpr int WHI_O = 20480;      // 32 k-rows x 528 (512B f16 n256 + pad)
constexpr int WC_O  = 37376;      // 256 n-rows x 80
constexpr int STG1  = 57856;
// H1 region (aliases stage-1 after layer 1):
constexpr int H1HI_O = 0;         // 128 x 528 f16
constexpr int H1C_O  = 67584;     // 128 x 528 fp8 blocks (16 kb x 32B + pad)
constexpr int R1     = 135168;
constexpr int STG2   = 37376;     // WHI(16896) + WC(20480)
constexpr int SMEM_TOTAL = R1 + 2 * STG2;  // 209920

// -------------------- preprocessed global scratch --------------------
// cross layouts are [kb16-major] so stage loads are contiguous spans:
//   g_xc : [kb (48)][row (4096)][32B]      g_w*c: [t][kb][n (256)][32B]
__device__ __align__(16) __half  g_xhi [(size_t)Bdim * INdim];
__device__ __align__(16) uint8_t g_xc  [(size_t)(INdim / 16) * Bdim * 32];
__device__ __align__(16) __half  g_w1hi[(size_t)Tdim * INdim * Hdim];
__device__ __align__(16) uint8_t g_w1c [(size_t)Tdim * (INdim / 16) * Hdim * 32];
__device__ __align__(16) __half  g_w2hi[(size_t)Tdim * Hdim * Hdim];
__device__ __align__(16) uint8_t g_w2c [(size_t)Tdim * (Hdim / 16) * Hdim * 32];

// ------------------------------ helpers ------------------------------
__device__ __forceinline__ uint16_t e4m3x2(float hi, float lo) {
    uint16_t r;  // byte0 = cvt(lo), byte1 = cvt(hi)
    asm("cvt.rn.satfinite.e4m3x2.f32 %0, %1, %2;" : "=h"(r) : "f"(hi), "f"(lo));
    return r;
}
__device__ __forceinline__ uint32_t s2u(const void* p) {
    return (uint32_t)__cvta_generic_to_shared(p);
}
__device__ __forceinline__ void cp16(uint32_t dst, const void* src) {
    asm volatile("cp.async.cg.shared.global [%0], [%1], 16;" :: "r"(dst), "l"(src));
}
__device__ __forceinline__ void cp_commit() {
    asm volatile("cp.async.commit_group;" ::: "memory");
}
__device__ __forceinline__ void cp_wait_all() {
    asm volatile("cp.async.wait_group 0;" ::: "memory");
}
__device__ __forceinline__ void ldm4(uint32_t (&r)[4], uint32_t a) {
    asm volatile("ldmatrix.sync.aligned.m8n8.x4.shared.b16 {%0,%1,%2,%3}, [%4];"
                 : "=r"(r[0]), "=r"(r[1]), "=r"(r[2]), "=r"(r[3]) : "r"(a));
}
__device__ __forceinline__ void ldm4t(uint32_t (&r)[4], uint32_t a) {
    asm volatile("ldmatrix.sync.aligned.m8n8.x4.trans.shared.b16 {%0,%1,%2,%3}, [%4];"
                 : "=r"(r[0]), "=r"(r[1]), "=r"(r[2]), "=r"(r[3]) : "r"(a));
}
__device__ __forceinline__ void mma_f16(float (&d)[4], const uint32_t (&a)[4],
                                        uint32_t b0, uint32_t b1) {
    asm volatile(
        "mma.sync.aligned.m16n8k16.row.col.f32.f16.f16.f32 "
        "{%0,%1,%2,%3}, {%4,%5,%6,%7}, {%8,%9}, {%0,%1,%2,%3};"
        : "+f"(d[0]), "+f"(d[1]), "+f"(d[2]), "+f"(d[3])
        : "r"(a[0]), "r"(a[1]), "r"(a[2]), "r"(a[3]), "r"(b0), "r"(b1));
}
__device__ __forceinline__ void mma_fp8(float (&d)[4], const uint32_t (&a)[4],
                                        uint32_t b0, uint32_t b1) {
    asm volatile(
        "mma.sync.aligned.m16n8k32.row.col.f32.e4m3.e4m3.f32 "
        "{%0,%1,%2,%3}, {%4,%5,%6,%7}, {%8,%9}, {%0,%1,%2,%3};"
        : "+f"(d[0]), "+f"(d[1]), "+f"(d[2]), "+f"(d[3])
        : "r"(a[0]), "r"(a[1]), "r"(a[2]), "r"(a[3]), "r"(b0), "r"(b1));
}

// ------------------------------ prep kernels ------------------------------
// X: per (row, kb16): f16 hi (layout preserved) + 32B fp8 A'-block [lo | hi].
__global__ void split_x(const float* __restrict__ x) {
    int g = blockIdx.x * 256 + threadIdx.x;
    if (g >= Bdim * (INdim / 16)) return;
    int kb = g / Bdim, row = g % Bdim;      // row fastest -> block writes coalesce
    const float* src = x + (size_t)row * INdim + kb * 16;
    float hf[16], lo[16];
    uint32_t hw[8];
#pragma unroll
    for (int q = 0; q < 8; q++) {
        float v0 = src[2 * q], v1 = src[2 * q + 1];
        __half h0 = __float2half_rn(v0), h1 = __float2half_rn(v1);
        hf[2 * q] = __half2float(h0); hf[2 * q + 1] = __half2float(h1);
        lo[2 * q] = v0 - hf[2 * q];   lo[2 * q + 1] = v1 - hf[2 * q + 1];
        __half2 p; p.x = h0; p.y = h1;
        hw[q] = *(uint32_t*)&p;
    }
    uint4* dhi = (uint4*)(g_xhi + (size_t)row * INdim + kb * 16);
    dhi[0] = make_uint4(hw[0], hw[1], hw[2], hw[3]);
    dhi[1] = make_uint4(hw[4], hw[5], hw[6], hw[7]);
    uint32_t loW[4], hiW[4];
#pragma unroll
    for (int q = 0; q < 4; q++) {
        loW[q] = (uint32_t)e4m3x2(lo[4 * q + 1] * ALO, lo[4 * q] * ALO) |
                 ((uint32_t)e4m3x2(lo[4 * q + 3] * ALO, lo[4 * q + 2] * ALO) << 16);
        hiW[q] = (uint32_t)e4m3x2(hf[4 * q + 1] * AHI, hf[4 * q] * AHI) |
                 ((uint32_t)e4m3x2(hf[4 * q + 3] * AHI, hf[4 * q + 2] * AHI) << 16);
    }
    uint4* dc = (uint4*)(g_xc + ((size_t)kb * Bdim + row) * 32);
    dc[0] = make_uint4(loW[0], loW[1], loW[2], loW[3]);
    dc[1] = make_uint4(hiW[0], hiW[1], hiW[2], hiW[3]);
}

// Fused W prep: read each 64x64 tile once; write f16-hi (coalesced, layout
// preserved [t][k][n]) and fp8 cross blocks [t][kb][n][ hi*4 16B | lo*2^13 16B ]
// with one full 32B block per thread (2x uint4, warp-contiguous in n).
template <int K, int WHICH>
__global__ void __launch_bounds__(256) wprep(const float* __restrict__ src) {
    __half*  ghi = WHICH ? g_w1hi : g_w2hi;
    uint8_t* gc  = WHICH ? g_w1c  : g_w2c;
    __shared__ float tile[64][68];
    const int t = blockIdx.z, k0 = blockIdx.x * 64, n0 = blockIdx.y * 64;
    const int tid = threadIdx.x;
    const float* s = src + (size_t)t * K * Hdim;

    // Phase A: read 64x64 floats, write f16*2^11 hi, stash to smem.
#pragma unroll
    for (int i = 0; i < 4; i++) {
        int idx = i * 256 + tid;
        int k = idx >> 4, c4 = (idx & 15) * 4;
        float4 v = *(const float4*)(s + (size_t)(k0 + k) * Hdim + n0 + c4);
        __half2 p0, p1;
        p0.x = __float2half_rn(v.x * SCL); p0.y = __float2half_rn(v.y * SCL);
        p1.x = __float2half_rn(v.z * SCL); p1.y = __float2half_rn(v.w * SCL);
        *(uint2*)(ghi + ((size_t)t * K + k0 + k) * Hdim + n0 + c4) =
            make_uint2(*(uint32_t*)&p0, *(uint32_t*)&p1);
        *(float4*)&tile[k][c4] = v;
    }
    __syncthreads();

    // Phase B: one 32B cross block per thread (16 k elems of one column).
    const int kb = tid >> 6, n = tid & 63;
    uint32_t hiW[4], loW[4];
#pragma unroll
    for (int q = 0; q < 4; q++) {
        float hf[4], lo[4];
#pragma unroll
        for (int jj = 0; jj < 4; jj++) {
            float v = tile[kb * 16 + q * 4 + jj][n];
            __half h = __float2half_rn(v);
            hf[jj] = __half2float(h);
            lo[jj] = v - hf[jj];
        }
        hiW[q] = (uint32_t)e4m3x2(hf[1] * BHI, hf[0] * BHI) |
                 ((uint32_t)e4m3x2(hf[3] * BHI, hf[2] * BHI) << 16);
        loW[q] = (uint32_t)e4m3x2(lo[1] * BLO, lo[0] * BLO) |
                 ((uint32_t)e4m3x2(lo[3] * BLO, lo[2] * BLO) << 16);
    }
    uint4* dst = (uint4*)(gc + (((size_t)t * (K / 16) + (k0 / 16 + kb)) * Hdim
                                + n0 + n) * 32);
    dst[0] = make_uint4(hiW[0], hiW[1], hiW[2], hiW[3]);
    dst[1] = make_uint4(loW[0], loW[1], loW[2], loW[3]);
}

// ------------------------------ main kernel ------------------------------
__global__ void __launch_bounds__(NTHR, 1)
mlp_kernel(const float* __restrict__ b1, const float* __restrict__ b2,
           const float* __restrict__ W3, const float* __restrict__ b3,
           float* __restrict__ out) {
    extern __shared__ char smem[];
    const uint32_t sb = s2u(smem);
    const int tid = threadIdx.x;
    const int lane = tid & 31, w = tid >> 5;
    const int wr = w >> 2, wc = w & 3;                   // 2x4 warps, 64x64 tiles
    const int t = blockIdx.y;
    const int gb0 = blockIdx.x * MT;

    const int lr  = (lane & 7) + 8 * ((lane >> 3) & 1);  // row-in-16 (A / Bt)
    const int lc8 = 8 * (lane >> 4);                     // 16B half select
    const int ncr = (lane & 7) + 8 * (lane >> 4);        // fp8 B: column row
    const int nbo = 16 * ((lane >> 3) & 1);              // fp8 B: k-half byte

    const __half*  xhi = g_xhi + (size_t)gb0 * INdim;
    const uint8_t* xc  = g_xc  + (size_t)gb0 * 32;
    const __half*  w1h = g_w1hi + (size_t)t * INdim * Hdim;
    const uint8_t* w1c = g_w1c  + (size_t)t * (INdim / 16) * Hdim * 32;
    const __half*  w2h = g_w2hi + (size_t)t * Hdim * Hdim;
    const uint8_t* w2c = g_w2c  + (size_t)t * (Hdim / 16) * Hdim * 32;

    float acc[4][8][4];
#pragma unroll
    for (int mi = 0; mi < 4; mi++)
#pragma unroll
        for (int ni = 0; ni < 8; ni++)
#pragma unroll
            for (int r = 0; r < 4; r++) acc[mi][ni][r] = 0.f;

    auto ld1 = [&](int s) {
        const uint32_t S = sb + ((s & 1) ? STG1 : 0);
        const int k0 = s * 32, kb0 = s * 2;
#pragma unroll
        for (int it = 0; it < 2; it++) {             // XHI: 128 rows x 64B
            int idx = it * NTHR + tid;
            int row = idx >> 2, c = (idx & 3) * 16;
            cp16(S + XHI_O + (uint32_t)(row * 80 + c),
                 (const char*)(xhi + (size_t)row * INdim + k0) + c);
        }
#pragma unroll
        for (int it = 0; it < 2; it++) {             // XC: 2 contiguous 4KB spans
            int idx = it * NTHR + tid;
            int j = idx >> 8, r2 = idx & 255, row = r2 >> 1, half = r2 & 1;
            cp16(S + XC_O + (uint32_t)(row * 80 + j * 32 + half * 16),
                 xc + ((size_t)(kb0 + j) * Bdim + row) * 32 + half * 16);
        }
#pragma unroll
        for (int it = 0; it < 4; it++) {             // WHI: 32 k-rows x 512B
            int idx = it * NTHR + tid;
            int row = idx >> 5, c = (idx & 31) * 16;
            cp16(S + WHI_O + (uint32_t)(row * 528 + c),
                 (const char*)(w1h + (size_t)(k0 + row) * Hdim) + c);
        }
#pragma unroll
        for (int it = 0; it < 4; it++) {             // WC: 2 contiguous 8KB spans
            int idx = it * NTHR + tid;
            int j = idx >> 9, r = idx & 511, n = r >> 1, half = r & 1;
            cp16(S + WC_O + (uint32_t)(n * 80 + j * 32 + half * 16),
                 w1c + ((size_t)(kb0 + j) * Hdim + n) * 32 + half * 16);
        }
        cp_commit();
    };
    auto ld2 = [&](int s) {
        const uint32_t S = sb + (uint32_t)(R1 + ((s & 1) ? STG2 : 0));
        const int k0 = s * 32, kb0 = s * 2;
#pragma unroll
        for (int it = 0; it < 4; it++) {
            int idx = it * NTHR + tid;
            int row = idx >> 5, c = (idx & 31) * 16;
            cp16(S + (uint32_t)(row * 528 + c),
                 (const char*)(w2h + (size_t)(k0 + row) * Hdim) + c);
        }
#pragma unroll
        for (int it = 0; it < 4; it++) {
            int idx = it * NTHR + tid;
            int j = idx >> 9, r = idx & 511, n = r >> 1, half = r & 1;
            cp16(S + 16896u + (uint32_t)(n * 80 + j * 32 + half * 16),
                 w2c + ((size_t)(kb0 + j) * Hdim + n) * 32 + half * 16);
        }
        cp_commit();
    };

    // one k16 slab = 32 f16 hh MMAs then 32 fp8 cross MMAs (shared scaled acc)
    auto slab = [&](uint32_t aHi, int aStride, uint32_t aCr, int aCrStride,
                    uint32_t wHi, uint32_t wCr) {
        uint32_t ah[4][4];
#pragma unroll
        for (int mi = 0; mi < 4; mi++)
            ldm4(ah[mi], aHi + (uint32_t)((wr * 64 + mi * 16 + lr) * aStride
                                          + 2 * lc8));
#pragma unroll
        for (int ni2 = 0; ni2 < 4; ni2++) {
            uint32_t bh[4];
            ldm4t(bh, wHi + (uint32_t)(lr * 528 + (wc * 64 + ni2 * 16 + lc8) * 2));
#pragma unroll
            for (int mi = 0; mi < 4; mi++) {
                mma_f16(acc[mi][2 * ni2],     ah[mi], bh[0], bh[1]);
                mma_f16(acc[mi][2 * ni2 + 1], ah[mi], bh[2], bh[3]);
            }
        }
        uint32_t ac[4][4];
#pragma unroll
        for (int mi = 0; mi < 4; mi++)
            ldm4(ac[mi], aCr + (uint32_t)((wr * 64 + mi * 16 + lr) * aCrStride
                                          + 2 * lc8));
#pragma unroll
        for (int ni2 = 0; ni2 < 4; ni2++) {
            uint32_t bc[4];
            ldm4(bc, wCr + (uint32_t)((wc * 64 + ni2 * 16 + ncr) * 80 + nbo));
#pragma unroll
            for (int mi = 0; mi < 4; mi++) {
                mma_fp8(acc[mi][2 * ni2],     ac[mi], bc[0], bc[1]);
                mma_fp8(acc[mi][2 * ni2 + 1], ac[mi], bc[2], bc[3]);
            }
        }
    };

    // ==================== Layer 1 (1 sync per stage) ====================
    ld1(0);
    for (int s = 0; s < NS1; s++) {
        cp_wait_all();
        __syncthreads();          // loads of s visible; compute of s-1 done
        if (s + 1 < NS1) ld1(s + 1);   // targets buffer freed by stage s-1
        const uint32_t S = sb + ((s & 1) ? STG1 : 0);
#pragma unroll
        for (int kk = 0; kk < 2; kk++)
            slab(S + XHI_O + kk * 32, 80, S + XC_O + kk * 32, 80,
                 S + WHI_O + (uint32_t)(kk * 16 * 528), S + WC_O + kk * 32);
    }
    __syncthreads();              // all layer-1 compute done; stage bufs dead
    ld2(0);                       // prefetch W2 stage 0 under epilogue 1

    // == Epilogue 1: descale, bias, relu; write H1 f16-hi + fp8 A' to smem ==
    {
        const float* b1t = b1 + t * Hdim;
#pragma unroll
        for (int mi = 0; mi < 4; mi++)
#pragma unroll
            for (int ni = 0; ni < 8; ni++) {
                const int c = wc * 64 + ni * 8 + (lane & 3) * 2;
                const float2 bb = *(const float2*)(b1t + c);
#pragma unroll
                for (int h = 0; h < 2; h++) {
                    const int row = wr * 64 + mi * 16 + (lane >> 2) + 8 * h;
                    float v0 = fmaxf(fmaf(acc[mi][ni][2 * h],     INV, bb.x), 0.f);
                    float v1 = fmaxf(fmaf(acc[mi][ni][2 * h + 1], INV, bb.y), 0.f);
                    __half h0 = __float2half_rn(v0), h1 = __float2half_rn(v1);
                    float f0 = __half2float(h0), f1 = __half2float(h1);
                    __half2 hp; hp.x = h0; hp.y = h1;
                    *(uint32_t*)(smem + H1HI_O + row * 528 + c * 2) = *(uint32_t*)&hp;
                    uint32_t co = H1C_O + row * 528 + (c >> 4) * 32 + (c & 15);
                    *(uint16_t*)(smem + co) =
                        e4m3x2((v1 - f1) * ALO, (v0 - f0) * ALO);
                    *(uint16_t*)(smem + co + 16) = e4m3x2(f1 * AHI, f0 * AHI);
                    acc[mi][ni][2 * h] = 0.f;
                    acc[mi][ni][2 * h + 1] = 0.f;
                }
            }
    }

    // ==================== Layer 2 (1 sync per stage) ====================
    for (int s = 0; s < NS2; s++) {
        cp_wait_all();
        __syncthreads();          // also orders epilogue-1 H1 writes vs reads
        if (s + 1 < NS2) ld2(s + 1);
        const uint32_t S = sb + (uint32_t)(R1 + ((s & 1) ? STG2 : 0));
#pragma unroll
        for (int kk = 0; kk < 2; kk++)
            slab(sb + H1HI_O + (uint32_t)((s * 32 + kk * 16) * 2), 528,
                 sb + H1C_O + (uint32_t)((s * 2 + kk) * 32), 528,
                 S + (uint32_t)(kk * 16 * 528), S + 16896u + kk * 32);
    }

    // ======= Epilogue 2 + Layer 3: out = relu(H2).W3 + b3 =======
    {
        const float* b2t = b2 + t * Hdim;
        const float* w3t = W3 + t * Hdim;
        float p[4][2];
#pragma unroll
        for (int mi = 0; mi < 4; mi++) { p[mi][0] = 0.f; p[mi][1] = 0.f; }
#pragma unroll
        for (int ni = 0; ni < 8; ni++) {
            const int c = wc * 64 + ni * 8 + (lane & 3) * 2;
            const float2 bb = *(const float2*)(b2t + c);
            const float2 ww = *(const float2*)(w3t + c);
#pragma unroll
            for (int mi = 0; mi < 4; mi++)
#pragma unroll
                for (int h = 0; h < 2; h++) {
                    float v0 = fmaxf(fmaf(acc[mi][ni][2 * h],     INV, bb.x), 0.f);
                    float v1 = fmaxf(fmaf(acc[mi][ni][2 * h + 1], INV, bb.y), 0.f);
                    p[mi][h] += v0 * ww.x + v1 * ww.y;
                }
        }
        float* red = (float*)(smem + R1);   // stage-2 bufs dead after last slab
        __syncthreads();
#pragma unroll
        for (int mi = 0; mi < 4; mi++)
#pragma unroll
            for (int h = 0; h < 2; h++) {
                float v = p[mi][h];
                v += __shfl_xor_sync(0xffffffffu, v, 1);
                v += __shfl_xor_sync(0xffffffffu, v, 2);
                if ((lane & 3) == 0) {
                    const int row = wr * 64 + mi * 16 + (lane >> 2) + 8 * h;
                    red[row * 4 + wc] = v;
                }
            }
        __syncthreads();
        if (tid < MT) {
            float s4 = red[tid * 4] + red[tid * 4 + 1] +
                       red[tid * 4 + 2] + red[tid * 4 + 3] + __ldg(b3 + t);
            out[(size_t)(gb0 + tid) * Tdim + t] = s4;
        }
    }
}

}  // namespace

extern "C" void kernel_launch(void* const* d_in, const int* in_sizes, int n_in,
                              void* d_out, int out_size) {
    const float* x  = (const float*)d_in[0];
    const float* W1 = (const float*)d_in[1];
    const float* b1 = (const float*)d_in[2];
    const float* W2 = (const float*)d_in[3];
    const float* b2 = (const float*)d_in[4];
    const float* W3 = (const float*)d_in[5];
    const float* b3 = (const float*)d_in[6];
    float* out = (float*)d_out;

    split_x<<<(Bdim * (INdim / 16) + 255) / 256, 256>>>(x);
    wprep<INdim, 1><<<dim3(INdim / 64, Hdim / 64, Tdim), 256>>>(W1);
    wprep<Hdim,  0><<<dim3(Hdim  / 64, Hdim / 64, Tdim), 256>>>(W2);

    cudaFuncSetAttribute(mlp_kernel,
                         cudaFuncAttributeMaxDynamicSharedMemorySize, SMEM_TOTAL);
    dim3 grid(Bdim / MT, Tdim);  // b-block fastest: wave shares few tasks' W in L2
    mlp_kernel<<<grid, NTHR, SMEM_TOTAL>>>(b1, b2, W3, b3, out);
}

// round 15
// speedup vs baseline: 1.7506x; 1.7179x over previous
#include <cuda_runtime.h>
#include <cuda_fp16.h>
#include <cstdint>

// MultiTaskMLP, 2-term f16 HMMA with A-operand splitting:
//   a*b ~= (a_hi + a_lo) * f16(b)    [a_hi+a_lo == a to ~2^-23; error = a*b_lo]
// Per-layer rel err ~ u_f16/sqrt(3) ~ 2.8e-4; two layers ~ 4e-4 < 1e-3.
// 2 f16 MMAs per k16 (vs 3 for bf16 hi/lo). W is plain f16, no transpose prep.
// One CTA = (task t, 128 rows of B); 8 warps of 64x64 tiles; H1 hi/lo in smem.

namespace {

constexpr int Bdim = 4096, Tdim = 128, INdim = 768, Hdim = 256;
constexpr int MT = 128, NTHR = 256;
constexpr int NS1 = INdim / 32;   // 24 k32 pipeline stages
constexpr int NS2 = Hdim / 32;    // 8

// smem layout (bytes)
constexpr int XS = 80;            // A stage row stride (64B data + 16 pad)
constexpr int WS = 528;           // W row stride (512B data + 16 pad); also H1
constexpr int XHI_O = 0;          // 128 x 80 = 10240
constexpr int XLO_O = 10240;      // 128 x 80 = 10240
constexpr int W_O   = 20480;      // 32 x 528 = 16896
constexpr int STG1  = 37376;      // one layer-1 stage buffer
constexpr int H1_O   = 2 * STG1;          // 74752  (H1 hi: 128 x 528)
constexpr int H1LO_O = H1_O + MT * WS;    // 142336 (H1 lo: 128 x 528)
constexpr int STG2  = 16896;      // layer-2 W2 stage buffer (aliases stage-1)
constexpr int SMEM_TOTAL = H1LO_O + MT * WS;  // 209920

// -------------------- prep outputs (device globals) --------------------
__device__ __align__(16) __half g_xhi[(size_t)Bdim * INdim];
__device__ __align__(16) __half g_xlo[(size_t)Bdim * INdim];
__device__ __align__(16) __half g_w1 [(size_t)Tdim * INdim * Hdim];  // [t][k][n]
__device__ __align__(16) __half g_w2 [(size_t)Tdim * Hdim * Hdim];   // [t][k][n]

// ------------------------------ helpers ------------------------------
__device__ __forceinline__ uint32_t s2u(const void* p) {
    return (uint32_t)__cvta_generic_to_shared(p);
}
__device__ __forceinline__ void cp16(uint32_t dst, const void* src) {
    asm volatile("cp.async.cg.shared.global [%0], [%1], 16;" :: "r"(dst), "l"(src));
}
__device__ __forceinline__ void cp_commit() {
    asm volatile("cp.async.commit_group;" ::: "memory");
}
__device__ __forceinline__ void cp_wait_all() {
    asm volatile("cp.async.wait_group 0;" ::: "memory");
}
__device__ __forceinline__ void ldm4(uint32_t (&r)[4], uint32_t a) {
    asm volatile("ldmatrix.sync.aligned.m8n8.x4.shared.b16 {%0,%1,%2,%3}, [%4];"
                 : "=r"(r[0]), "=r"(r[1]), "=r"(r[2]), "=r"(r[3]) : "r"(a));
}
__device__ __forceinline__ void ldm4t(uint32_t (&r)[4], uint32_t a) {
    asm volatile("ldmatrix.sync.aligned.m8n8.x4.trans.shared.b16 {%0,%1,%2,%3}, [%4];"
                 : "=r"(r[0]), "=r"(r[1]), "=r"(r[2]), "=r"(r[3]) : "r"(a));
}
__device__ __forceinline__ void mma_f16(float (&d)[4], const uint32_t (&a)[4],
                                        uint32_t b0, uint32_t b1) {
    asm volatile(
        "mma.sync.aligned.m16n8k16.row.col.f32.f16.f16.f32 "
        "{%0,%1,%2,%3}, {%4,%5,%6,%7}, {%8,%9}, {%0,%1,%2,%3};"
        : "+f"(d[0]), "+f"(d[1]), "+f"(d[2]), "+f"(d[3])
        : "r"(a[0]), "r"(a[1]), "r"(a[2]), "r"(a[3]), "r"(b0), "r"(b1));
}

// ------------------------------ prep kernels ------------------------------
// NOTE: device globals are referenced ONLY inside device code (host-side
// symbol addresses are invalid — that was the round-13 bug).
__global__ void split_x_f16(const float* __restrict__ x, int n4) {
    int i = blockIdx.x * 256 + threadIdx.x;
    if (i >= n4) return;
    float4 v = ((const float4*)x)[i];
    __half2 h0, h1, l0, l1;
    h0.x = __float2half_rn(v.x); h0.y = __float2half_rn(v.y);
    h1.x = __float2half_rn(v.z); h1.y = __float2half_rn(v.w);
    l0.x = __float2half_rn(v.x - __half2float(h0.x));
    l0.y = __float2half_rn(v.y - __half2float(h0.y));
    l1.x = __float2half_rn(v.z - __half2float(h1.x));
    l1.y = __float2half_rn(v.w - __half2float(h1.y));
    ((uint2*)g_xhi)[i] = make_uint2(*(uint32_t*)&h0, *(uint32_t*)&h1);
    ((uint2*)g_xlo)[i] = make_uint2(*(uint32_t*)&l0, *(uint32_t*)&l1);
}
__global__ void cvt_w_f16(const float* __restrict__ src, int which, int n4) {
    int i = blockIdx.x * 256 + threadIdx.x;
    if (i >= n4) return;
    uint2* dst = which ? (uint2*)g_w1 : (uint2*)g_w2;
    float4 v = ((const float4*)src)[i];
    __half2 p0, p1;
    p0.x = __float2half_rn(v.x); p0.y = __float2half_rn(v.y);
    p1.x = __float2half_rn(v.z); p1.y = __float2half_rn(v.w);
    dst[i] = make_uint2(*(uint32_t*)&p0, *(uint32_t*)&p1);
}

// ------------------------------ main kernel ------------------------------
__global__ void __launch_bounds__(NTHR, 1)
mlp_kernel(const float* __restrict__ b1, const float* __restrict__ b2,
           const float* __restrict__ W3, const float* __restrict__ b3,
           float* __restrict__ out) {
    extern __shared__ char smem[];
    const uint32_t sb = s2u(smem);
    const int tid = threadIdx.x;
    const int lane = tid & 31, w = tid >> 5;
    const int wr = w >> 2, wc = w & 3;                   // 2x4 warps, 64x64 tiles
    const int t = blockIdx.y;
    const int gb0 = blockIdx.x * MT;

    const int lr  = (lane & 7) + 8 * ((lane >> 3) & 1);  // row-in-16 (A / Bt)
    const int lc8 = 8 * (lane >> 4);                     // 16B half select

    const __half* xhi = g_xhi + (size_t)gb0 * INdim;
    const __half* xlo = g_xlo + (size_t)gb0 * INdim;
    const __half* w1p = g_w1 + (size_t)t * INdim * Hdim;
    const __half* w2p = g_w2 + (size_t)t * Hdim * Hdim;

    float acc[4][8][4];
#pragma unroll
    for (int mi = 0; mi < 4; mi++)
#pragma unroll
        for (int ni = 0; ni < 8; ni++)
#pragma unroll
            for (int r = 0; r < 4; r++) acc[mi][ni][r] = 0.f;

    auto ld1 = [&](int s) {
        const uint32_t S = sb + ((s & 1) ? STG1 : 0);
        const int k0 = s * 32;
#pragma unroll
        for (int it = 0; it < 2; it++) {             // X hi + lo: 128 rows x 64B
            int idx = it * NTHR + tid;
            int row = idx >> 2, c = (idx & 3) * 16;
            cp16(S + XHI_O + (uint32_t)(row * XS + c),
                 (const char*)(xhi + (size_t)row * INdim + k0) + c);
            cp16(S + XLO_O + (uint32_t)(row * XS + c),
                 (const char*)(xlo + (size_t)row * INdim + k0) + c);
        }
#pragma unroll
        for (int it = 0; it < 4; it++) {             // W1: 32 k-rows x 512B
            int idx = it * NTHR + tid;
            int row = idx >> 5, c = (idx & 31) * 16;
            cp16(S + W_O + (uint32_t)(row * WS + c),
                 (const char*)(w1p + (size_t)(k0 + row) * Hdim) + c);
        }
        cp_commit();
    };
    auto ld2 = [&](int s) {
        const uint32_t S = sb + ((s & 1) ? STG2 : 0);
        const int k0 = s * 32;
#pragma unroll
        for (int it = 0; it < 4; it++) {             // W2: 32 k-rows x 512B
            int idx = it * NTHR + tid;
            int row = idx >> 5, c = (idx & 31) * 16;
            cp16(S + (uint32_t)(row * WS + c),
                 (const char*)(w2p + (size_t)(k0 + row) * Hdim) + c);
        }
        cp_commit();
    };

    // one k16 slab = 8 A-ldmatrix (hi+lo) + 4 B-ldmatrix + 64 f16 MMAs
    // (all 32 hi MMAs then all 32 lo MMAs -> same-acc reuse distance 32)
    auto slab = [&](uint32_t aHi, uint32_t aLo, int aStride, uint32_t wBase) {
        uint32_t ah[4][4], al[4][4], bh[4][4];
#pragma unroll
        for (int mi = 0; mi < 4; mi++) {
            const uint32_t ro = (uint32_t)((wr * 64 + mi * 16 + lr) * aStride
                                           + 2 * lc8);
            ldm4(ah[mi], aHi + ro);
            ldm4(al[mi], aLo + ro);
        }
#pragma unroll
        for (int ni2 = 0; ni2 < 4; ni2++)
            ldm4t(bh[ni2],
                  wBase + (uint32_t)(lr * WS + (wc * 64 + ni2 * 16 + lc8) * 2));
#pragma unroll
        for (int ni2 = 0; ni2 < 4; ni2++)
#pragma unroll
            for (int mi = 0; mi < 4; mi++) {
                mma_f16(acc[mi][2 * ni2],     ah[mi], bh[ni2][0], bh[ni2][1]);
                mma_f16(acc[mi][2 * ni2 + 1], ah[mi], bh[ni2][2], bh[ni2][3]);
            }
#pragma unroll
        for (int ni2 = 0; ni2 < 4; ni2++)
#pragma unroll
            for (int mi = 0; mi < 4; mi++) {
                mma_f16(acc[mi][2 * ni2],     al[mi], bh[ni2][0], bh[ni2][1]);
                mma_f16(acc[mi][2 * ni2 + 1], al[mi], bh[ni2][2], bh[ni2][3]);
            }
    };

    // ==================== Layer 1 (1 sync per stage) ====================
    ld1(0);
    for (int s = 0; s < NS1; s++) {
        cp_wait_all();
        __syncthreads();               // stage-s loads visible; s-1 compute done
        if (s + 1 < NS1) ld1(s + 1);   // targets buffer freed by stage s-1
        const uint32_t S = sb + ((s & 1) ? STG1 : 0);
#pragma unroll
        for (int kk = 0; kk < 2; kk++)
            slab(S + XHI_O + kk * 32, S + XLO_O + kk * 32, XS,
                 S + W_O + (uint32_t)(kk * 16 * WS));
    }
    __syncthreads();                   // layer-1 compute done; stage bufs dead
    ld2(0);                            // prefetch W2 stage 0 under epilogue 1

    // ==== Epilogue 1: bias + relu -> H1 split to f16 hi/lo in smem ====
    {
        const float* b1t = b1 + t * Hdim;
#pragma unroll
        for (int mi = 0; mi < 4; mi++)
#pragma unroll
            for (int ni = 0; ni < 8; ni++) {
                const int c = wc * 64 + ni * 8 + (lane & 3) * 2;
                const float2 bb = *(const float2*)(b1t + c);
#pragma unroll
                for (int h = 0; h < 2; h++) {
                    const int row = wr * 64 + mi * 16 + (lane >> 2) + 8 * h;
                    float v0 = fmaxf(acc[mi][ni][2 * h]     + bb.x, 0.f);
                    float v1 = fmaxf(acc[mi][ni][2 * h + 1] + bb.y, 0.f);
                    __half2 hp, lp;
                    hp.x = __float2half_rn(v0);
                    hp.y = __float2half_rn(v1);
                    lp.x = __float2half_rn(v0 - __half2float(hp.x));
                    lp.y = __float2half_rn(v1 - __half2float(hp.y));
                    const uint32_t off = (uint32_t)(row * WS + c * 2);
                    *(uint32_t*)(smem + H1_O + off)   = *(uint32_t*)&hp;
                    *(uint32_t*)(smem + H1LO_O + off) = *(uint32_t*)&lp;
                    acc[mi][ni][2 * h] = 0.f;
                    acc[mi][ni][2 * h + 1] = 0.f;
                }
            }
    }

    // ==================== Layer 2 (1 sync per stage) ====================
    for (int s = 0; s < NS2; s++) {
        cp_wait_all();
        __syncthreads();               // also orders epilogue-1 H1 writes
        if (s + 1 < NS2) ld2(s + 1);
        const uint32_t S = sb + ((s & 1) ? STG2 : 0);
#pragma unroll
        for (int kk = 0; kk < 2; kk++)
            slab(sb + H1_O + (uint32_t)((s * 32 + kk * 16) * 2),
                 sb + H1LO_O + (uint32_t)((s * 32 + kk * 16) * 2), WS,
                 S + (uint32_t)(kk * 16 * WS));
    }

    // ======= Epilogue 2 + Layer 3: out = relu(H2).W3 + b3 =======
    {
        const float* b2t = b2 + t * Hdim;
        const float* w3t = W3 + t * Hdim;
        float p[4][2];
#pragma unroll
        for (int mi = 0; mi < 4; mi++) { p[mi][0] = 0.f; p[mi][1] = 0.f; }
#pragma unroll
        for (int ni = 0; ni < 8; ni++) {
            const int c = wc * 64 + ni * 8 + (lane & 3) * 2;
            const float2 bb = *(const float2*)(b2t + c);
            const float2 ww = *(const float2*)(w3t + c);
#pragma unroll
            for (int mi = 0; mi < 4; mi++)
#pragma unroll
                for (int h = 0; h < 2; h++) {
                    float v0 = fmaxf(acc[mi][ni][2 * h]     + bb.x, 0.f);
                    float v1 = fmaxf(acc[mi][ni][2 * h + 1] + bb.y, 0.f);
                    p[mi][h] += v0 * ww.x + v1 * ww.y;
                }
        }
        float* red = (float*)smem;     // stage bufs dead after last slab
        __syncthreads();
#pragma unroll
        for (int mi = 0; mi < 4; mi++)
#pragma unroll
            for (int h = 0; h < 2; h++) {
                float v = p[mi][h];
                v += __shfl_xor_sync(0xffffffffu, v, 1);
                v += __shfl_xor_sync(0xffffffffu, v, 2);
                if ((lane & 3) == 0) {
                    const int row = wr * 64 + mi * 16 + (lane >> 2) + 8 * h;
                    red[row * 4 + wc] = v;
                }
            }
        __syncthreads();
        if (tid < MT) {
            float s4 = red[tid * 4] + red[tid * 4 + 1] +
                       red[tid * 4 + 2] + red[tid * 4 + 3] + __ldg(b3 + t);
            out[(size_t)(gb0 + tid) * Tdim + t] = s4;
        }
    }
}

}  // namespace

extern "C" void kernel_launch(void* const* d_in, const int* in_sizes, int n_in,
                              void* d_out, int out_size) {
    const float* x  = (const float*)d_in[0];
    const float* W1 = (const float*)d_in[1];
    const float* b1 = (const float*)d_in[2];
    const float* W2 = (const float*)d_in[3];
    const float* b2 = (const float*)d_in[4];
    const float* W3 = (const float*)d_in[5];
    const float* b3 = (const float*)d_in[6];
    float* out = (float*)d_out;

    const int nx  = Bdim * INdim / 4;
    const int nw1 = Tdim * INdim * Hdim / 4;
    const int nw2 = Tdim * Hdim * Hdim / 4;
    split_x_f16<<<(nx + 255) / 256, 256>>>(x, nx);
    cvt_w_f16<<<(nw1 + 255) / 256, 256>>>(W1, 1, nw1);
    cvt_w_f16<<<(nw2 + 255) / 256, 256>>>(W2, 0, nw2);

    cudaFuncSetAttribute(mlp_kernel,
                         cudaFuncAttributeMaxDynamicSharedMemorySize, SMEM_TOTAL);
    dim3 grid(Bdim / MT, Tdim);  // b-block fastest: wave shares few tasks' W in L2
    mlp_kernel<<<grid, NTHR, SMEM_TOTAL>>>(b1, b2, W3, b3, out);
}

// round 16
// speedup vs baseline: 1.9557x; 1.1172x over previous
#include <cuda_runtime.h>
#include <cuda_fp16.h>
#include <cstdint>

// MultiTaskMLP, 2-term f16 HMMA with A-operand splitting:
//   a*b ~= (a_hi + a_lo) * f16(b)   [error = a*b_lo ~ u_f16; total ~3e-4]
// R16: MT=64 rows/CTA, 2 CTAs/SM (occ 25%) so one CTA's MMAs cover the other
// CTA's stage-barrier bubbles. Warp tile 32x64, acc 64 regs, smem 99KB/CTA.

namespace {

constexpr int Bdim = 4096, Tdim = 128, INdim = 768, Hdim = 256;
constexpr int MT = 64, NTHR = 256;
constexpr int NS1 = INdim / 32;   // 24 k32 pipeline stages
constexpr int NS2 = Hdim / 32;    // 8

// smem layout (bytes)
constexpr int XS = 80;            // A stage row stride (64B data + 16 pad)
constexpr int WS = 528;           // W row stride (512B data + 16 pad); also H1
constexpr int XHI_O = 0;          // 64 x 80 = 5120
constexpr int XLO_O = 5120;       // 64 x 80 = 5120
constexpr int W_O   = 10240;      // 32 x 528 = 16896
constexpr int STG1  = 27136;      // one layer-1 stage buffer (x2 = 54272)
// H1 aliases the layer-1 stage buffers (dead after layer-1 compute):
constexpr int H1_O   = 0;                 // H1 hi: 64 x 528 = 33792
constexpr int H1LO_O = 33792;             // H1 lo: 64 x 528 = 33792
constexpr int STG2_BASE = 67584;          // W2 stages: 2 x 16896
constexpr int STG2  = 16896;
constexpr int SMEM_TOTAL = STG2_BASE + 2 * STG2;  // 101376 -> 2 CTAs/SM

// -------------------- prep outputs (device globals) --------------------
__device__ __align__(16) __half g_xhi[(size_t)Bdim * INdim];
__device__ __align__(16) __half g_xlo[(size_t)Bdim * INdim];
__device__ __align__(16) __half g_w1 [(size_t)Tdim * INdim * Hdim];  // [t][k][n]
__device__ __align__(16) __half g_w2 [(size_t)Tdim * Hdim * Hdim];   // [t][k][n]

// ------------------------------ helpers ------------------------------
__device__ __forceinline__ uint32_t s2u(const void* p) {
    return (uint32_t)__cvta_generic_to_shared(p);
}
__device__ __forceinline__ void cp16(uint32_t dst, const void* src) {
    asm volatile("cp.async.cg.shared.global [%0], [%1], 16;" :: "r"(dst), "l"(src));
}
__device__ __forceinline__ void cp_commit() {
    asm volatile("cp.async.commit_group;" ::: "memory");
}
__device__ __forceinline__ void cp_wait_all() {
    asm volatile("cp.async.wait_group 0;" ::: "memory");
}
__device__ __forceinline__ void ldm4(uint32_t (&r)[4], uint32_t a) {
    asm volatile("ldmatrix.sync.aligned.m8n8.x4.shared.b16 {%0,%1,%2,%3}, [%4];"
                 : "=r"(r[0]), "=r"(r[1]), "=r"(r[2]), "=r"(r[3]) : "r"(a));
}
__device__ __forceinline__ void ldm4t(uint32_t (&r)[4], uint32_t a) {
    asm volatile("ldmatrix.sync.aligned.m8n8.x4.trans.shared.b16 {%0,%1,%2,%3}, [%4];"
                 : "=r"(r[0]), "=r"(r[1]), "=r"(r[2]), "=r"(r[3]) : "r"(a));
}
__device__ __forceinline__ void mma_f16(float (&d)[4], const uint32_t (&a)[4],
                                        uint32_t b0, uint32_t b1) {
    asm volatile(
        "mma.sync.aligned.m16n8k16.row.col.f32.f16.f16.f32 "
        "{%0,%1,%2,%3}, {%4,%5,%6,%7}, {%8,%9}, {%0,%1,%2,%3};"
        : "+f"(d[0]), "+f"(d[1]), "+f"(d[2]), "+f"(d[3])
        : "r"(a[0]), "r"(a[1]), "r"(a[2]), "r"(a[3]), "r"(b0), "r"(b1));
}

// ------------------------------ prep kernels ------------------------------
// Device globals referenced only inside device code (host symbol addr invalid).
__global__ void split_x_f16(const float* __restrict__ x, int n4) {
    int i = blockIdx.x * 256 + threadIdx.x;
    if (i >= n4) return;
    float4 v = ((const float4*)x)[i];
    __half2 h0, h1, l0, l1;
    h0.x = __float2half_rn(v.x); h0.y = __float2half_rn(v.y);
    h1.x = __float2half_rn(v.z); h1.y = __float2half_rn(v.w);
    l0.x = __float2half_rn(v.x - __half2float(h0.x));
    l0.y = __float2half_rn(v.y - __half2float(h0.y));
    l1.x = __float2half_rn(v.z - __half2float(h1.x));
    l1.y = __float2half_rn(v.w - __half2float(h1.y));
    ((uint2*)g_xhi)[i] = make_uint2(*(uint32_t*)&h0, *(uint32_t*)&h1);
    ((uint2*)g_xlo)[i] = make_uint2(*(uint32_t*)&l0, *(uint32_t*)&l1);
}
__global__ void cvt_w_f16(const float* __restrict__ src, int which, int n4) {
    int i = blockIdx.x * 256 + threadIdx.x;
    if (i >= n4) return;
    uint2* dst = which ? (uint2*)g_w1 : (uint2*)g_w2;
    float4 v = ((const float4*)src)[i];
    __half2 p0, p1;
    p0.x = __float2half_rn(v.x); p0.y = __float2half_rn(v.y);
    p1.x = __float2half_rn(v.z); p1.y = __float2half_rn(v.w);
    dst[i] = make_uint2(*(uint32_t*)&p0, *(uint32_t*)&p1);
}

// ------------------------------ main kernel ------------------------------
__global__ void __launch_bounds__(NTHR, 2)
mlp_kernel(const float* __restrict__ b1, const float* __restrict__ b2,
           const float* __restrict__ W3, const float* __restrict__ b3,
           float* __restrict__ out) {
    extern __shared__ char smem[];
    const uint32_t sb = s2u(smem);
    const int tid = threadIdx.x;
    const int lane = tid & 31, w = tid >> 5;
    const int wr = w >> 2, wc = w & 3;                   // 2x4 warps, 32x64 tiles
    const int t = blockIdx.y;
    const int gb0 = blockIdx.x * MT;

    const int lr  = (lane & 7) + 8 * ((lane >> 3) & 1);  // row-in-16 (A / Bt)
    const int lc8 = 8 * (lane >> 4);                     // 16B half select

    const __half* xhi = g_xhi + (size_t)gb0 * INdim;
    const __half* xlo = g_xlo + (size_t)gb0 * INdim;
    const __half* w1p = g_w1 + (size_t)t * INdim * Hdim;
    const __half* w2p = g_w2 + (size_t)t * Hdim * Hdim;

    float acc[2][8][4];
#pragma unroll
    for (int mi = 0; mi < 2; mi++)
#pragma unroll
        for (int ni = 0; ni < 8; ni++)
#pragma unroll
            for (int r = 0; r < 4; r++) acc[mi][ni][r] = 0.f;

    auto ld1 = [&](int s) {
        const uint32_t S = sb + ((s & 1) ? STG1 : 0);
        const int k0 = s * 32;
        {   // X hi + lo: 64 rows x 64B each (256 cp16 apiece)
            int row = tid >> 2, c = (tid & 3) * 16;
            cp16(S + XHI_O + (uint32_t)(row * XS + c),
                 (const char*)(xhi + (size_t)row * INdim + k0) + c);
            cp16(S + XLO_O + (uint32_t)(row * XS + c),
                 (const char*)(xlo + (size_t)row * INdim + k0) + c);
        }
#pragma unroll
        for (int it = 0; it < 4; it++) {             // W1: 32 k-rows x 512B
            int idx = it * NTHR + tid;
            int row = idx >> 5, c = (idx & 31) * 16;
            cp16(S + W_O + (uint32_t)(row * WS + c),
                 (const char*)(w1p + (size_t)(k0 + row) * Hdim) + c);
        }
        cp_commit();
    };
    auto ld2 = [&](int s) {
        const uint32_t S = sb + (uint32_t)(STG2_BASE + ((s & 1) ? STG2 : 0));
        const int k0 = s * 32;
#pragma unroll
        for (int it = 0; it < 4; it++) {             // W2: 32 k-rows x 512B
            int idx = it * NTHR + tid;
            int row = idx >> 5, c = (idx & 31) * 16;
            cp16(S + (uint32_t)(row * WS + c),
                 (const char*)(w2p + (size_t)(k0 + row) * Hdim) + c);
        }
        cp_commit();
    };

    // one k16 slab = 4 A-ldmatrix (hi+lo) + 4 B-ldmatrix + 32 f16 MMAs
    // (all 16 hi MMAs then all 16 lo MMAs -> same-acc reuse distance 16)
    auto slab = [&](uint32_t aHi, uint32_t aLo, int aStride, uint32_t wBase) {
        uint32_t ah[2][4], al[2][4], bh[4][4];
#pragma unroll
        for (int mi = 0; mi < 2; mi++) {
            const uint32_t ro = (uint32_t)((wr * 32 + mi * 16 + lr) * aStride
                                           + 2 * lc8);
            ldm4(ah[mi], aHi + ro);
            ldm4(al[mi], aLo + ro);
        }
#pragma unroll
        for (int ni2 = 0; ni2 < 4; ni2++)
            ldm4t(bh[ni2],
                  wBase + (uint32_t)(lr * WS + (wc * 64 + ni2 * 16 + lc8) * 2));
#pragma unroll
        for (int ni2 = 0; ni2 < 4; ni2++)
#pragma unroll
            for (int mi = 0; mi < 2; mi++) {
                mma_f16(acc[mi][2 * ni2],     ah[mi], bh[ni2][0], bh[ni2][1]);
                mma_f16(acc[mi][2 * ni2 + 1], ah[mi], bh[ni2][2], bh[ni2][3]);
            }
#pragma unroll
        for (int ni2 = 0; ni2 < 4; ni2++)
#pragma unroll
            for (int mi = 0; mi < 2; mi++) {
                mma_f16(acc[mi][2 * ni2],     al[mi], bh[ni2][0], bh[ni2][1]);
                mma_f16(acc[mi][2 * ni2 + 1], al[mi], bh[ni2][2], bh[ni2][3]);
            }
    };

    // ==================== Layer 1 (1 sync per stage) ====================
    ld1(0);
    for (int s = 0; s < NS1; s++) {
        cp_wait_all();
        __syncthreads();               // stage-s loads visible; s-1 compute done
        if (s + 1 < NS1) ld1(s + 1);   // targets buffer freed by stage s-1
        const uint32_t S = sb + ((s & 1) ? STG1 : 0);
#pragma unroll
        for (int kk = 0; kk < 2; kk++)
            slab(S + XHI_O + kk * 32, S + XLO_O + kk * 32, XS,
                 S + W_O + (uint32_t)(kk * 16 * WS));
    }
    __syncthreads();                   // layer-1 compute done; stage bufs dead
    ld2(0);                            // prefetch W2 stage 0 under epilogue 1

    // ==== Epilogue 1: bias + relu -> H1 split to f16 hi/lo in smem ====
    {
        const float* b1t = b1 + t * Hdim;
#pragma unroll
        for (int mi = 0; mi < 2; mi++)
#pragma unroll
            for (int ni = 0; ni < 8; ni++) {
                const int c = wc * 64 + ni * 8 + (lane & 3) * 2;
                const float2 bb = *(const float2*)(b1t + c);
#pragma unroll
                for (int h = 0; h < 2; h++) {
                    const int row = wr * 32 + mi * 16 + (lane >> 2) + 8 * h;
                    float v0 = fmaxf(acc[mi][ni][2 * h]     + bb.x, 0.f);
                    float v1 = fmaxf(acc[mi][ni][2 * h + 1] + bb.y, 0.f);
                    __half2 hp, lp;
                    hp.x = __float2half_rn(v0);
                    hp.y = __float2half_rn(v1);
                    lp.x = __float2half_rn(v0 - __half2float(hp.x));
                    lp.y = __float2half_rn(v1 - __half2float(hp.y));
                    const uint32_t off = (uint32_t)(row * WS + c * 2);
                    *(uint32_t*)(smem + H1_O + off)   = *(uint32_t*)&hp;
                    *(uint32_t*)(smem + H1LO_O + off) = *(uint32_t*)&lp;
                    acc[mi][ni][2 * h] = 0.f;
                    acc[mi][ni][2 * h + 1] = 0.f;
                }
            }
    }

    // ==================== Layer 2 (1 sync per stage) ====================
    for (int s = 0; s < NS2; s++) {
        cp_wait_all();
        __syncthreads();               // also orders epilogue-1 H1 writes
        if (s + 1 < NS2) ld2(s + 1);
        const uint32_t S = sb + (uint32_t)(STG2_BASE + ((s & 1) ? STG2 : 0));
#pragma unroll
        for (int kk = 0; kk < 2; kk++)
            slab(sb + H1_O + (uint32_t)((s * 32 + kk * 16) * 2),
                 sb + H1LO_O + (uint32_t)((s * 32 + kk * 16) * 2), WS,
                 S + (uint32_t)(kk * 16 * WS));
    }

    // ======= Epilogue 2 + Layer 3: out = relu(H2).W3 + b3 =======
    {
        const float* b2t = b2 + t * Hdim;
        const float* w3t = W3 + t * Hdim;
        float p[2][2];
#pragma unroll
        for (int mi = 0; mi < 2; mi++) { p[mi][0] = 0.f; p[mi][1] = 0.f; }
#pragma unroll
        for (int ni = 0; ni < 8; ni++) {
            const int c = wc * 64 + ni * 8 + (lane & 3) * 2;
            const float2 bb = *(const float2*)(b2t + c);
            const float2 ww = *(const float2*)(w3t + c);
#pragma unroll
            for (int mi = 0; mi < 2; mi++)
#pragma unroll
                for (int h = 0; h < 2; h++) {
                    float v0 = fmaxf(acc[mi][ni][2 * h]     + bb.x, 0.f);
                    float v1 = fmaxf(acc[mi][ni][2 * h + 1] + bb.y, 0.f);
                    p[mi][h] += v0 * ww.x + v1 * ww.y;
                }
        }
        float* red = (float*)smem;     // stage bufs dead after last slab
        __syncthreads();
#pragma unroll
        for (int mi = 0; mi < 2; mi++)
#pragma unroll
            for (int h = 0; h < 2; h++) {
                float v = p[mi][h];
                v += __shfl_xor_sync(0xffffffffu, v, 1);
                v += __shfl_xor_sync(0xffffffffu, v, 2);
                if ((lane & 3) == 0) {
                    const int row = wr * 32 + mi * 16 + (lane >> 2) + 8 * h;
                    red[row * 4 + wc] = v;
                }
            }
        __syncthreads();
        if (tid < MT) {
            float s4 = red[tid * 4] + red[tid * 4 + 1] +
                       red[tid * 4 + 2] + red[tid * 4 + 3] + __ldg(b3 + t);
            out[(size_t)(gb0 + tid) * Tdim + t] = s4;
        }
    }
}

}  // namespace

extern "C" void kernel_launch(void* const* d_in, const int* in_sizes, int n_in,
                              void* d_out, int out_size) {
    const float* x  = (const float*)d_in[0];
    const float* W1 = (const float*)d_in[1];
    const float* b1 = (const float*)d_in[2];
    const float* W2 = (const float*)d_in[3];
    const float* b2 = (const float*)d_in[4];
    const float* W3 = (const float*)d_in[5];
    const float* b3 = (const float*)d_in[6];
    float* out = (float*)d_out;

    const int nx  = Bdim * INdim / 4;
    const int nw1 = Tdim * INdim * Hdim / 4;
    const int nw2 = Tdim * Hdim * Hdim / 4;
    split_x_f16<<<(nx + 255) / 256, 256>>>(x, nx);
    cvt_w_f16<<<(nw1 + 255) / 256, 256>>>(W1, 1, nw1);
    cvt_w_f16<<<(nw2 + 255) / 256, 256>>>(W2, 0, nw2);

    cudaFuncSetAttribute(mlp_kernel,
                         cudaFuncAttributeMaxDynamicSharedMemorySize, SMEM_TOTAL);
    dim3 grid(Bdim / MT, Tdim);  // b-block fastest: co-resident CTAs share a task
    mlp_kernel<<<grid, NTHR, SMEM_TOTAL>>>(b1, b2, W3, b3, out);
}

// round 17
// speedup vs baseline: 3.1776x; 1.6248x over previous
#include <cuda_runtime.h>
#include <cuda_fp16.h>
#include <cstdint>

// MultiTaskMLP, single-term f16 HMMA (m16n8k16, fp32 acc).
// Calibrated error model: 2-term (W-rounding only) measured 2.98e-4; adding
// X/H1 rounding => sqrt(2)*2.98e-4 ~ 4.2e-4 < 1e-3. Half the MMAs of R16.
// k64 pipeline stages (half the barriers). MT=64 rows/CTA, 2 CTAs/SM.

namespace {

constexpr int Bdim = 4096, Tdim = 128, INdim = 768, Hdim = 256;
constexpr int MT = 64, NTHR = 256;
constexpr int NS1 = INdim / 64;   // 12 k64 pipeline stages
constexpr int NS2 = Hdim / 64;    // 4

// smem layout (bytes)
constexpr int XS = 144;           // X stage row stride (128B data + 16 pad)
constexpr int WS = 528;           // W row stride (512B data + 16 pad); also H1
constexpr int X_O  = 0;           // 64 x 144 = 9216
constexpr int W_O  = 9216;        // 64 x 528 = 33792
constexpr int STG1 = 43008;       // one layer-1 stage buffer (x2 = 86016)
// layer-2 region aliases the (dead) layer-1 stage buffers:
constexpr int H1_O = 0;                   // H1: 64 x 528 = 33792 (single f16)
constexpr int STG2_BASE = 33792;          // W2 stages: 2 x 33792
constexpr int STG2 = 33792;
constexpr int SMEM_TOTAL = STG2_BASE + 2 * STG2;  // 101376 -> 2 CTAs/SM

// -------------------- prep outputs (device globals) --------------------
__device__ __align__(16) __half g_xh[(size_t)Bdim * INdim];
__device__ __align__(16) __half g_w1[(size_t)Tdim * INdim * Hdim];  // [t][k][n]
__device__ __align__(16) __half g_w2[(size_t)Tdim * Hdim * Hdim];   // [t][k][n]

// ------------------------------ helpers ------------------------------
__device__ __forceinline__ uint32_t s2u(const void* p) {
    return (uint32_t)__cvta_generic_to_shared(p);
}
__device__ __forceinline__ void cp16(uint32_t dst, const void* src) {
    asm volatile("cp.async.cg.shared.global [%0], [%1], 16;" :: "r"(dst), "l"(src));
}
__device__ __forceinline__ void cp_commit() {
    asm volatile("cp.async.commit_group;" ::: "memory");
}
__device__ __forceinline__ void cp_wait_all() {
    asm volatile("cp.async.wait_group 0;" ::: "memory");
}
__device__ __forceinline__ void ldm4(uint32_t (&r)[4], uint32_t a) {
    asm volatile("ldmatrix.sync.aligned.m8n8.x4.shared.b16 {%0,%1,%2,%3}, [%4];"
                 : "=r"(r[0]), "=r"(r[1]), "=r"(r[2]), "=r"(r[3]) : "r"(a));
}
__device__ __forceinline__ void ldm4t(uint32_t (&r)[4], uint32_t a) {
    asm volatile("ldmatrix.sync.aligned.m8n8.x4.trans.shared.b16 {%0,%1,%2,%3}, [%4];"
                 : "=r"(r[0]), "=r"(r[1]), "=r"(r[2]), "=r"(r[3]) : "r"(a));
}
__device__ __forceinline__ void mma_f16(float (&d)[4], const uint32_t (&a)[4],
                                        uint32_t b0, uint32_t b1) {
    asm volatile(
        "mma.sync.aligned.m16n8k16.row.col.f32.f16.f16.f32 "
        "{%0,%1,%2,%3}, {%4,%5,%6,%7}, {%8,%9}, {%0,%1,%2,%3};"
        : "+f"(d[0]), "+f"(d[1]), "+f"(d[2]), "+f"(d[3])
        : "r"(a[0]), "r"(a[1]), "r"(a[2]), "r"(a[3]), "r"(b0), "r"(b1));
}

// ------------------------------ prep kernels ------------------------------
// Device globals referenced only inside device code (host symbol addr invalid).
__global__ void cvt_f16(const float* __restrict__ src, int which, int n4) {
    int i = blockIdx.x * 256 + threadIdx.x;
    if (i >= n4) return;
    uint2* dst = (which == 0) ? (uint2*)g_xh
               : (which == 1) ? (uint2*)g_w1 : (uint2*)g_w2;
    float4 v = ((const float4*)src)[i];
    __half2 p0, p1;
    p0.x = __float2half_rn(v.x); p0.y = __float2half_rn(v.y);
    p1.x = __float2half_rn(v.z); p1.y = __float2half_rn(v.w);
    dst[i] = make_uint2(*(uint32_t*)&p0, *(uint32_t*)&p1);
}

// ------------------------------ main kernel ------------------------------
__global__ void __launch_bounds__(NTHR, 2)
mlp_kernel(const float* __restrict__ b1, const float* __restrict__ b2,
           const float* __restrict__ W3, const float* __restrict__ b3,
           float* __restrict__ out) {
    extern __shared__ char smem[];
    const uint32_t sb = s2u(smem);
    const int tid = threadIdx.x;
    const int lane = tid & 31, w = tid >> 5;
    const int wr = w >> 2, wc = w & 3;                   // 2x4 warps, 32x64 tiles
    const int t = blockIdx.y;
    const int gb0 = blockIdx.x * MT;

    const int lr  = (lane & 7) + 8 * ((lane >> 3) & 1);  // row-in-16 (A / Bt)
    const int lc8 = 8 * (lane >> 4);                     // 16B half select

    const __half* xh  = g_xh + (size_t)gb0 * INdim;
    const __half* w1p = g_w1 + (size_t)t * INdim * Hdim;
    const __half* w2p = g_w2 + (size_t)t * Hdim * Hdim;

    float acc[2][8][4];
#pragma unroll
    for (int mi = 0; mi < 2; mi++)
#pragma unroll
        for (int ni = 0; ni < 8; ni++)
#pragma unroll
            for (int r = 0; r < 4; r++) acc[mi][ni][r] = 0.f;

    auto ld1 = [&](int s) {
        const uint32_t S = sb + ((s & 1) ? STG1 : 0);
        const int k0 = s * 64;
#pragma unroll
        for (int it = 0; it < 2; it++) {             // X: 64 rows x 128B
            int idx = it * NTHR + tid;
            int row = idx >> 3, c = (idx & 7) * 16;
            cp16(S + X_O + (uint32_t)(row * XS + c),
                 (const char*)(xh + (size_t)row * INdim + k0) + c);
        }
#pragma unroll
        for (int it = 0; it < 8; it++) {             // W1: 64 k-rows x 512B
            int idx = it * NTHR + tid;
            int row = idx >> 5, c = (idx & 31) * 16;
            cp16(S + W_O + (uint32_t)(row * WS + c),
                 (const char*)(w1p + (size_t)(k0 + row) * Hdim) + c);
        }
        cp_commit();
    };
    auto ld2 = [&](int s) {
        const uint32_t S = sb + (uint32_t)(STG2_BASE + ((s & 1) ? STG2 : 0));
        const int k0 = s * 64;
#pragma unroll
        for (int it = 0; it < 8; it++) {             // W2: 64 k-rows x 512B
            int idx = it * NTHR + tid;
            int row = idx >> 5, c = (idx & 31) * 16;
            cp16(S + (uint32_t)(row * WS + c),
                 (const char*)(w2p + (size_t)(k0 + row) * Hdim) + c);
        }
        cp_commit();
    };

    // one k16 slab = 2 A-ldmatrix + 4 B-ldmatrix + 16 f16 MMAs
    auto slab = [&](uint32_t aBase, int aStride, uint32_t wBase) {
        uint32_t ah[2][4], bh[4][4];
#pragma unroll
        for (int mi = 0; mi < 2; mi++)
            ldm4(ah[mi], aBase + (uint32_t)((wr * 32 + mi * 16 + lr) * aStride
                                            + 2 * lc8));
#pragma unroll
        for (int ni2 = 0; ni2 < 4; ni2++)
            ldm4t(bh[ni2],
                  wBase + (uint32_t)(lr * WS + (wc * 64 + ni2 * 16 + lc8) * 2));
#pragma unroll
        for (int ni2 = 0; ni2 < 4; ni2++)
#pragma unroll
            for (int mi = 0; mi < 2; mi++) {
                mma_f16(acc[mi][2 * ni2],     ah[mi], bh[ni2][0], bh[ni2][1]);
                mma_f16(acc[mi][2 * ni2 + 1], ah[mi], bh[ni2][2], bh[ni2][3]);
            }
    };

    // ==================== Layer 1 (1 sync per k64 stage) ====================
    ld1(0);
    for (int s = 0; s < NS1; s++) {
        cp_wait_all();
        __syncthreads();               // stage-s loads visible; s-1 compute done
        if (s + 1 < NS1) ld1(s + 1);   // targets buffer freed by stage s-1
        const uint32_t S = sb + ((s & 1) ? STG1 : 0);
#pragma unroll
        for (int kk = 0; kk < 4; kk++)
            slab(S + X_O + kk * 32, XS,
                 S + W_O + (uint32_t)(kk * 16 * WS));
    }
    __syncthreads();                   // layer-1 compute done; stage bufs dead
    ld2(0);                            // prefetch W2 stage 0 under epilogue 1

    // ======== Epilogue 1: bias + relu -> H1 (f16) in smem ========
    {
        const float* b1t = b1 + t * Hdim;
#pragma unroll
        for (int mi = 0; mi < 2; mi++)
#pragma unroll
            for (int ni = 0; ni < 8; ni++) {
                const int c = wc * 64 + ni * 8 + (lane & 3) * 2;
                const float2 bb = *(const float2*)(b1t + c);
#pragma unroll
                for (int h = 0; h < 2; h++) {
                    const int row = wr * 32 + mi * 16 + (lane >> 2) + 8 * h;
                    float v0 = fmaxf(acc[mi][ni][2 * h]     + bb.x, 0.f);
                    float v1 = fmaxf(acc[mi][ni][2 * h + 1] + bb.y, 0.f);
                    __half2 hp;
                    hp.x = __float2half_rn(v0);
                    hp.y = __float2half_rn(v1);
                    *(uint32_t*)(smem + H1_O + row * WS + c * 2) = *(uint32_t*)&hp;
                    acc[mi][ni][2 * h] = 0.f;
                    acc[mi][ni][2 * h + 1] = 0.f;
                }
            }
    }

    // ==================== Layer 2 (1 sync per k64 stage) ====================
    for (int s = 0; s < NS2; s++) {
        cp_wait_all();
        __syncthreads();               // also orders epilogue-1 H1 writes
        if (s + 1 < NS2) ld2(s + 1);
        const uint32_t S = sb + (uint32_t)(STG2_BASE + ((s & 1) ? STG2 : 0));
#pragma unroll
        for (int kk = 0; kk < 4; kk++)
            slab(sb + H1_O + (uint32_t)((s * 64 + kk * 16) * 2), WS,
                 S + (uint32_t)(kk * 16 * WS));
    }

    // ======= Epilogue 2 + Layer 3: out = relu(H2).W3 + b3 =======
    {
        const float* b2t = b2 + t * Hdim;
        const float* w3t = W3 + t * Hdim;
        float p[2][2];
#pragma unroll
        for (int mi = 0; mi < 2; mi++) { p[mi][0] = 0.f; p[mi][1] = 0.f; }
#pragma unroll
        for (int ni = 0; ni < 8; ni++) {
            const int c = wc * 64 + ni * 8 + (lane & 3) * 2;
            const float2 bb = *(const float2*)(b2t + c);
            const float2 ww = *(const float2*)(w3t + c);
#pragma unroll
            for (int mi = 0; mi < 2; mi++)
#pragma unroll
                for (int h = 0; h < 2; h++) {
                    float v0 = fmaxf(acc[mi][ni][2 * h]     + bb.x, 0.f);
                    float v1 = fmaxf(acc[mi][ni][2 * h + 1] + bb.y, 0.f);
                    p[mi][h] += v0 * ww.x + v1 * ww.y;
                }
        }
        float* red = (float*)smem;     // stage bufs dead after last slab
        __syncthreads();
#pragma unroll
        for (int mi = 0; mi < 2; mi++)
#pragma unroll
            for (int h = 0; h < 2; h++) {
                float v = p[mi][h];
                v += __shfl_xor_sync(0xffffffffu, v, 1);
                v += __shfl_xor_sync(0xffffffffu, v, 2);
                if ((lane & 3) == 0) {
                    const int row = wr * 32 + mi * 16 + (lane >> 2) + 8 * h;
                    red[row * 4 + wc] = v;
                }
            }
        __syncthreads();
        if (tid < MT) {
            float s4 = red[tid * 4] + red[tid * 4 + 1] +
                       red[tid * 4 + 2] + red[tid * 4 + 3] + __ldg(b3 + t);
            out[(size_t)(gb0 + tid) * Tdim + t] = s4;
        }
    }
}

}  // namespace

extern "C" void kernel_launch(void* const* d_in, const int* in_sizes, int n_in,
                              void* d_out, int out_size) {
    const float* x  = (const float*)d_in[0];
    const float* W1 = (const float*)d_in[1];
    const float* b1 = (const float*)d_in[2];
    const float* W2 = (const float*)d_in[3];
    const float* b2 = (const float*)d_in[4];
    const float* W3 = (const float*)d_in[5];
    const float* b3 = (const float*)d_in[6];
    float* out = (float*)d_out;

    const int nx  = Bdim * INdim / 4;
    const int nw1 = Tdim * INdim * Hdim / 4;
    const int nw2 = Tdim * Hdim * Hdim / 4;
    cvt_f16<<<(nx  + 255) / 256, 256>>>(x,  0, nx);
    cvt_f16<<<(nw1 + 255) / 256, 256>>>(W1, 1, nw1);
    cvt_f16<<<(nw2 + 255) / 256, 256>>>(W2, 2, nw2);

    cudaFuncSetAttribute(mlp_kernel,
                         cudaFuncAttributeMaxDynamicSharedMemorySize, SMEM_TOTAL);
    dim3 grid(Bdim / MT, Tdim);  // b-block fastest: co-resident CTAs share a task
    mlp_kernel<<<grid, NTHR, SMEM_TOTAL>>>(b1, b2, W3, b3, out);
}